// round 11
// baseline (speedup 1.0000x reference)
#include <cuda_runtime.h>
#include <cuda_bf16.h>
#include <cstdint>

// ---------------------------------------------------------------------------
// RNN: out[b,t,:] = sigmoid(x@K + h_{t-1}@Wr),  B=64, T=512, D=H=1024
// ONE fused launch, 152 CTAs x 512 threads:
//   pre-phase : ALL 152 CTAs drain a dynamic xh-tile queue (full-chip GEMM)
//   recurrence: CTAs 0..127 (2 M-halves x 64 N-tiles) run 512 steps with a
//               TREE grid barrier (16 groups of 8 -> root). CTAs 128+ exit.
// Per-SMSP recurrence mma halves vs R10 (128 CTAs instead of 64).
// ---------------------------------------------------------------------------

#define BATCH 64
#define TSEQ  512
#define DIM   1024

#define NCTA_TOTAL 152
#define NPERS      128           // recurrence CTAs (2 x 64)
#define NTILES     2048          // xh tiles: 256 M x 8 N

// ---- recurrence geometry ----
#define NTILE  16                // N cols per CTA
#define BS_STRIDE 1028
#define BS_WORDS  (NTILE * BS_STRIDE)          // 16448
#define A_STRIDE  36                           // 32 + 4 pad
#define ABUF_WORDS (32 * A_STRIDE)             // chunk: 32 rows x 32 cols
#define A_REGION_WORDS (16 * 2 * ABUF_WORDS)   // 36864
#define FUSED_SMEM_BYTES ((BS_WORDS + A_REGION_WORDS) * 4)   // 213,248 B

// ---- gemm geometry (512 thr: warp grid 4M x 4N, warp tile 32x32) ----
#define G_BM 128
#define G_BN 128
#define G_BK 32
#define GA_STRIDE 36
#define GB_STRIDE 132
#define G_STAGE_WORDS (G_BM * GA_STRIDE + G_BK * GB_STRIDE)   // 8832
#define G_BCAST (2 * G_STAGE_WORDS)                           // bcast slot

__device__ float g_xh[(size_t)BATCH * TSEQ * DIM];
__device__ unsigned g_tile;       // gemm tile queue head
__device__ unsigned g_tdone;      // gemm tiles completed
__device__ unsigned g_grp[16];    // barrier group counters
__device__ unsigned g_root;       // barrier root counter
__device__ unsigned g_sense;      // barrier sense

__device__ __forceinline__ uint32_t f2tf32(float x) {
    uint32_t r;
    asm("cvt.rna.tf32.f32 %0, %1;" : "=r"(r) : "f"(x));
    return r;
}

__device__ __forceinline__ void mma_tf32(float* d,
                                         uint32_t a0, uint32_t a1, uint32_t a2, uint32_t a3,
                                         uint32_t b0, uint32_t b1) {
    asm volatile(
        "mma.sync.aligned.m16n8k8.row.col.f32.tf32.tf32.f32 "
        "{%0,%1,%2,%3}, {%4,%5,%6,%7}, {%8,%9}, {%0,%1,%2,%3};\n"
        : "+f"(d[0]), "+f"(d[1]), "+f"(d[2]), "+f"(d[3])
        : "r"(a0), "r"(a1), "r"(a2), "r"(a3), "r"(b0), "r"(b1));
}

__device__ __forceinline__ float sigmoidf_fast(float z) {
    return 1.0f / (1.0f + __expf(-z));
}

__device__ __forceinline__ void cp16(uint32_t smem_addr, const void* gsrc) {
    asm volatile("cp.async.cg.shared.global [%0], [%1], 16;\n"
                 :: "r"(smem_addr), "l"(gsrc));
}
__device__ __forceinline__ void cp_commit() {
    asm volatile("cp.async.commit_group;\n" ::: "memory");
}
template <int N>
__device__ __forceinline__ void cp_wait() {
    asm volatile("cp.async.wait_group %0;\n" :: "n"(N) : "memory");
}

// ---------------------------------------------------------------------------
__global__ void reset_state_kernel() {
    if (threadIdx.x < 16) g_grp[threadIdx.x] = 0u;
    if (threadIdx.x == 16) g_root = 0u;
    if (threadIdx.x == 17) g_sense = 0u;
    if (threadIdx.x == 18) g_tile = 0u;
    if (threadIdx.x == 19) g_tdone = 0u;
}

// ---------------------------------------------------------------------------
// Tree grid barrier across NPERS CTAs: 16 groups of 8 -> root of 16.
// Parity sense per step; counters self-reset -> launch-invariant.
// ---------------------------------------------------------------------------
__device__ __forceinline__ void tree_barrier(int bid, int tid, int t) {
    __syncthreads();
    if (tid == 0) {
        const unsigned ns = ((unsigned)t & 1u) ^ 1u;
        __threadfence();
        unsigned old;
        asm volatile("atom.acq_rel.gpu.global.add.u32 %0, [%1], %2;"
                     : "=r"(old) : "l"(&g_grp[bid >> 3]), "r"(1u) : "memory");
        if (old == 7u) {
            asm volatile("st.relaxed.gpu.global.u32 [%0], %1;"
                         :: "l"(&g_grp[bid >> 3]), "r"(0u) : "memory");
            unsigned rold;
            asm volatile("atom.acq_rel.gpu.global.add.u32 %0, [%1], %2;"
                         : "=r"(rold) : "l"(&g_root), "r"(1u) : "memory");
            if (rold == 15u) {
                asm volatile("st.relaxed.gpu.global.u32 [%0], %1;"
                             :: "l"(&g_root), "r"(0u) : "memory");
                asm volatile("st.release.gpu.global.u32 [%0], %1;"
                             :: "l"(&g_sense), "r"(ns) : "memory");
            } else {
                unsigned v;
                do {
                    asm volatile("ld.acquire.gpu.global.u32 %0, [%1];"
                                 : "=r"(v) : "l"(&g_sense) : "memory");
                } while (v != ns);
            }
        } else {
            unsigned v;
            do {
                asm volatile("ld.acquire.gpu.global.u32 %0, [%1];"
                             : "=r"(v) : "l"(&g_sense) : "memory");
            } while (v != ns);
        }
    }
    __syncthreads();
}

// ---------------------------------------------------------------------------
// GEMM pre-phase: dynamic tile queue over all CTAs (512 threads each).
// tile: bm = (tile>>3)*128 rows of [32768], bn = (tile&7)*128.
// ---------------------------------------------------------------------------
__device__ void gemm_phase(uint32_t* gsm, const float* __restrict__ X,
                           const float* __restrict__ W) {
    const int tid  = threadIdx.x;
    const int lane = tid & 31;
    const int wid  = tid >> 5;
    const int wm   = (wid & 3) * 32;
    const int wn   = (wid >> 2) * 32;
    const int gid  = lane >> 2;
    const int tg   = lane & 3;

    auto As = [&](int s) { return gsm + s * G_STAGE_WORDS; };
    auto Bs = [&](int s) { return gsm + s * G_STAGE_WORDS + G_BM * GA_STRIDE; };

    for (;;) {
        if (tid == 0) gsm[G_BCAST] = atomicAdd(&g_tile, 1u);
        __syncthreads();
        const unsigned tile = gsm[G_BCAST];
        if (tile >= NTILES) break;

        const int bm = (int)(tile >> 3) * G_BM;
        const int bn = (int)(tile & 7) * G_BN;

        auto issue = [&](int k0, int s) {
            uint32_t abase = (uint32_t)__cvta_generic_to_shared(As(s));
            uint32_t bbase = (uint32_t)__cvta_generic_to_shared(Bs(s));
            #pragma unroll
            for (int i = 0; i < 2; i++) {
                int idx = tid + i * 512;
                int r = idx >> 3;
                int c = (idx & 7) * 4;
                cp16(abase + (r * GA_STRIDE + c) * 4,
                     X + (size_t)(bm + r) * DIM + k0 + c);
            }
            #pragma unroll
            for (int i = 0; i < 2; i++) {
                int idx = tid + i * 512;
                int r = idx >> 5;
                int c = (idx & 31) * 4;
                cp16(bbase + (r * GB_STRIDE + c) * 4,
                     W + (size_t)(k0 + r) * DIM + bn + c);
            }
            cp_commit();
        };

        float acc[2][4][4];
        #pragma unroll
        for (int mt = 0; mt < 2; mt++)
            #pragma unroll
            for (int nt = 0; nt < 4; nt++)
                #pragma unroll
                for (int i = 0; i < 4; i++) acc[mt][nt][i] = 0.0f;

        issue(0, 0);
        issue(G_BK, 1);

        const int NKITER = DIM / G_BK;
        for (int kb = 0; kb < NKITER; kb++) {
            if (kb < NKITER - 1) cp_wait<1>(); else cp_wait<0>();
            __syncthreads();

            const uint32_t* A = As(kb & 1);
            const uint32_t* B = Bs(kb & 1);

            #pragma unroll
            for (int k8 = 0; k8 < G_BK; k8 += 8) {
                uint32_t a[2][4], b[4][2];
                #pragma unroll
                for (int mt = 0; mt < 2; mt++) {
                    int r = (wm + mt * 16 + gid) * GA_STRIDE;
                    a[mt][0] = A[r + k8 + tg];
                    a[mt][1] = A[r + 8 * GA_STRIDE + k8 + tg];
                    a[mt][2] = A[r + k8 + tg + 4];
                    a[mt][3] = A[r + 8 * GA_STRIDE + k8 + tg + 4];
                }
                #pragma unroll
                for (int nt = 0; nt < 4; nt++) {
                    int c = wn + nt * 8 + gid;
                    b[nt][0] = B[(k8 + tg) * GB_STRIDE + c];
                    b[nt][1] = B[(k8 + tg + 4) * GB_STRIDE + c];
                }
                #pragma unroll
                for (int mt = 0; mt < 2; mt++)
                    #pragma unroll
                    for (int nt = 0; nt < 4; nt++)
                        mma_tf32(acc[mt][nt], a[mt][0], a[mt][1], a[mt][2], a[mt][3],
                                 b[nt][0], b[nt][1]);
            }
            __syncthreads();
            if (kb + 2 < NKITER) issue((kb + 2) * G_BK, kb & 1);
        }

        #pragma unroll
        for (int mt = 0; mt < 2; mt++) {
            #pragma unroll
            for (int nt = 0; nt < 4; nt++) {
                int r = bm + wm + mt * 16 + gid;
                int c = bn + wn + nt * 8 + tg * 2;
                *(float2*)(&g_xh[(size_t)r * DIM + c]) =
                    make_float2(acc[mt][nt][0], acc[mt][nt][1]);
                *(float2*)(&g_xh[(size_t)(r + 8) * DIM + c]) =
                    make_float2(acc[mt][nt][2], acc[mt][nt][3]);
            }
        }

        __threadfence();
        __syncthreads();   // all threads' stores fenced; also guards G_BCAST reuse
        if (tid == 0) {
            asm volatile("red.release.gpu.global.add.u32 [%0], %1;"
                         :: "l"(&g_tdone), "r"(1u) : "memory");
        }
    }
    __syncthreads();
}

// ---------------------------------------------------------------------------
// Recurrence: 128 CTAs x 512 thr. CTA bid: mhalf = bid>>6 (rows [mhalf*32,+32)),
// bn = (bid&63)*16. 16 warps = K-sixteenths (64 cols each); warp streams its
// 32x64 A region in 2 chunks of 32x32 via a private 2-buffer ring.
// 16-way K reduction via aliased SMEM scratch -> flat epilogue -> tree barrier.
// ---------------------------------------------------------------------------
__device__ void pers_path(uint32_t* smem, const float* __restrict__ Wr,
                          float* __restrict__ OUT, int bid) {
    uint32_t* Bsm  = smem;
    uint32_t* Abuf = smem + BS_WORDS;
    float*    Scr  = (float*)Abuf;

    const int tid   = threadIdx.x;
    const int lane  = tid & 31;
    const int wid   = tid >> 5;
    const int mhalf = bid >> 6;            // 0..1
    const int bn    = (bid & 63) * NTILE;
    const int rbase = mhalf * 32;          // batch-row base
    const int ks    = wid;                 // K-sixteenth 0..15
    const int kbase = ks * 64;
    const int gid   = lane >> 2;
    const int tg    = lane & 3;

    // Wr slice -> SMEM transposed [n][k], RNA tf32
    for (int idx = tid; idx < NTILE * DIM; idx += 512) {
        int n = idx & (NTILE - 1);
        int k = idx >> 4;
        Bsm[n * BS_STRIDE + k] = f2tf32(Wr[(size_t)k * DIM + bn + n]);
    }
    __syncthreads();

    // wait for ALL xh tiles
    if (tid == 0) {
        unsigned v;
        do {
            asm volatile("ld.acquire.gpu.global.u32 %0, [%1];"
                         : "=r"(v) : "l"(&g_tdone) : "memory");
        } while (v < NTILES);
    }
    __syncthreads();

    const uint32_t* Aw = Abuf + wid * 2 * ABUF_WORDS;
    const uint32_t warp_sb = (uint32_t)__cvta_generic_to_shared(Abuf)
                           + wid * 2 * ABUF_WORDS * 4;

    for (int t = 0; t < TSEQ; t++) {
        float acc[2][2][2][4];   // [chain][mt][nt][frag]
        #pragma unroll
        for (int ch = 0; ch < 2; ch++)
            #pragma unroll
            for (int mt = 0; mt < 2; mt++)
                #pragma unroll
                for (int nt = 0; nt < 2; nt++)
                    #pragma unroll
                    for (int i = 0; i < 4; i++) acc[ch][mt][nt][i] = 0.0f;

        if (t > 0) {
            const float* Hprev = OUT + (size_t)(t - 1) * DIM;

            // chunk c (0..1): 32 rows x 32 cols (4 KB) = 8 cp16/lane
            auto issue = [&](int c) {
                const int k0 = kbase + c * 32;
                const uint32_t base = warp_sb + (c & 1) * ABUF_WORDS * 4;
                #pragma unroll
                for (int i = 0; i < 8; i++) {
                    int idx = lane + i * 32;
                    int r  = idx >> 3;        // 0..31
                    int c4 = idx & 7;         // 0..7
                    cp16(base + (r * A_STRIDE + c4 * 4) * 4,
                         Hprev + (size_t)(rbase + r) * (TSEQ * DIM) + k0 + c4 * 4);
                }
                cp_commit();
            };

            issue(0);
            issue(1);

            #pragma unroll
            for (int c = 0; c < 2; c++) {
                if (c == 0) cp_wait<1>(); else cp_wait<0>();
                __syncwarp();

                const uint32_t* Ab = Aw + (c & 1) * ABUF_WORDS;
                const int kb = kbase + c * 32;

                #pragma unroll
                for (int k8i = 0; k8i < 4; k8i++) {
                    const int kk = k8i * 8;
                    const int ch = k8i & 1;
                    uint32_t a[2][4];
                    #pragma unroll
                    for (int mt = 0; mt < 2; mt++) {
                        int lr = (mt * 16 + gid) * A_STRIDE;
                        a[mt][0] = Ab[lr + kk + tg];
                        a[mt][1] = Ab[lr + 8 * A_STRIDE + kk + tg];
                        a[mt][2] = Ab[lr + kk + tg + 4];
                        a[mt][3] = Ab[lr + 8 * A_STRIDE + kk + tg + 4];
                    }
                    #pragma unroll
                    for (int nt = 0; nt < 2; nt++) {
                        int n = nt * 8 + gid;
                        uint32_t b0 = Bsm[n * BS_STRIDE + kb + kk + tg];
                        uint32_t b1 = Bsm[n * BS_STRIDE + kb + kk + tg + 4];
                        #pragma unroll
                        for (int mt = 0; mt < 2; mt++)
                            mma_tf32(acc[ch][mt][nt], a[mt][0], a[mt][1],
                                     a[mt][2], a[mt][3], b0, b1);
                    }
                }
            }
        }

        float accf[2][2][4];
        #pragma unroll
        for (int mt = 0; mt < 2; mt++)
            #pragma unroll
            for (int nt = 0; nt < 2; nt++)
                #pragma unroll
                for (int i = 0; i < 4; i++)
                    accf[mt][nt][i] = acc[0][mt][nt][i] + acc[1][mt][nt][i];

        __syncthreads();   // compute done before scratch aliases rings

        // partial store: P[ks][row 0..31][col 0..15]  (512 floats per ks)
        #pragma unroll
        for (int mt = 0; mt < 2; mt++) {
            int rg = mt * 16 + gid;           // 0..15 / 16..23? -> 0..15,16..31 via +8 below
            #pragma unroll
            for (int nt = 0; nt < 2; nt++) {
                int off = ks * 512 + rg * 16 + nt * 8 + tg * 2;
                *(float2*)&Scr[off]       = make_float2(accf[mt][nt][0], accf[mt][nt][1]);
                *(float2*)&Scr[off + 128] = make_float2(accf[mt][nt][2], accf[mt][nt][3]);
            }
        }
        __syncthreads();

        // flat epilogue: 512 threads x 1 output (row = tid>>4, col = tid&15)
        {
            int o   = tid;
            int row = o >> 4;
            int col = o & 15;
            float s = 0.0f;
            #pragma unroll
            for (int p = 0; p < 16; p++) s += Scr[p * 512 + o];
            size_t go = ((size_t)(rbase + row) * TSEQ + t) * DIM + bn + col;
            OUT[go] = sigmoidf_fast(s + g_xh[go]);
        }

        tree_barrier(bid, tid, t);
    }
}

// ---------------------------------------------------------------------------
__global__ __launch_bounds__(512, 1) void fused_rnn(const float* __restrict__ X,
                                                    const float* __restrict__ W,
                                                    const float* __restrict__ Wr,
                                                    float* __restrict__ OUT) {
    extern __shared__ uint32_t smem[];
    const int bid = blockIdx.x;

    // pre-phase: full-chip xh GEMM via dynamic tile queue
    gemm_phase(smem, X, W);

    // recurrence on CTAs 0..127; others exit
    if (bid < NPERS) pers_path(smem, Wr, OUT, bid);
}

// ---------------------------------------------------------------------------
extern "C" void kernel_launch(void* const* d_in, const int* in_sizes, int n_in,
                              void* d_out, int out_size) {
    const float* x  = (const float*)d_in[0];  // [64, 512, 1024]
    const float* w  = (const float*)d_in[1];  // [1024, 1024]
    const float* wr = (const float*)d_in[2];  // [1024, 1024]
    float* out = (float*)d_out;               // [64, 512, 1024]

    cudaFuncSetAttribute(fused_rnn,
                         cudaFuncAttributeMaxDynamicSharedMemorySize,
                         FUSED_SMEM_BYTES);

    reset_state_kernel<<<1, 32>>>();
    fused_rnn<<<NCTA_TOTAL, 512, FUSED_SMEM_BYTES>>>(x, w, wr, out);
}

// round 12
// speedup vs baseline: 1.0657x; 1.0657x over previous
#include <cuda_runtime.h>
#include <cuda_bf16.h>
#include <cstdint>

// ---------------------------------------------------------------------------
// RNN: out[b,t,:] = sigmoid(x@K + h_{t-1}@Wr),  B=64, T=512, D=H=1024
// ONE fused launch, 152 CTAs x 512 threads, hybrid schedule:
//   Phase A: ALL CTAs drain quarter-0 xh tiles (dynamic queue)   (~110us)
//   Phase B: CTAs 0..127 run the recurrence (2 M-halves x 64 N-tiles,
//            INDEPENDENT per-half tree barriers); CTAs 128..151 keep
//            computing xh quarters 1..3, signaling g_qdone[q].
// ---------------------------------------------------------------------------

#define BATCH 64
#define TSEQ  512
#define DIM   1024

#define NCTA_TOTAL 152
#define NPERS      128
#define NTILES     2048
#define TILES_PER_Q 512

// ---- recurrence geometry (R11) ----
#define NTILE  16
#define BS_STRIDE 1028
#define BS_WORDS  (NTILE * BS_STRIDE)          // 16448
#define A_STRIDE  36
#define ABUF_WORDS (32 * A_STRIDE)
#define A_REGION_WORDS (16 * 2 * ABUF_WORDS)   // 36864
#define FUSED_SMEM_BYTES ((BS_WORDS + A_REGION_WORDS) * 4)   // 213,248 B

// ---- gemm geometry (512 thr: warp grid 4M x 4N, warp tile 32x32) ----
#define G_BM 128
#define G_BN 128
#define G_BK 32
#define GA_STRIDE 36
#define GB_STRIDE 132
#define G_STAGE_WORDS (G_BM * GA_STRIDE + G_BK * GB_STRIDE)   // 8832
#define G_BCAST (2 * G_STAGE_WORDS)

__device__ float g_xh[(size_t)BATCH * TSEQ * DIM];
__device__ unsigned g_tileA;      // phase-A queue (quarter 0)
__device__ unsigned g_tileB;      // phase-B queue (quarters 1..3), starts at 512
__device__ unsigned g_qdone[4];   // tiles completed per quarter
__device__ unsigned g_grp[16];    // barrier group counters (8 per half)
__device__ unsigned g_root[2];    // per-half root counters
__device__ unsigned g_sense[2];   // per-half sense

__device__ __forceinline__ uint32_t f2tf32(float x) {
    uint32_t r;
    asm("cvt.rna.tf32.f32 %0, %1;" : "=r"(r) : "f"(x));
    return r;
}

__device__ __forceinline__ void mma_tf32(float* d,
                                         uint32_t a0, uint32_t a1, uint32_t a2, uint32_t a3,
                                         uint32_t b0, uint32_t b1) {
    asm volatile(
        "mma.sync.aligned.m16n8k8.row.col.f32.tf32.tf32.f32 "
        "{%0,%1,%2,%3}, {%4,%5,%6,%7}, {%8,%9}, {%0,%1,%2,%3};\n"
        : "+f"(d[0]), "+f"(d[1]), "+f"(d[2]), "+f"(d[3])
        : "r"(a0), "r"(a1), "r"(a2), "r"(a3), "r"(b0), "r"(b1));
}

__device__ __forceinline__ float sigmoidf_fast(float z) {
    return 1.0f / (1.0f + __expf(-z));
}

__device__ __forceinline__ void cp16(uint32_t smem_addr, const void* gsrc) {
    asm volatile("cp.async.cg.shared.global [%0], [%1], 16;\n"
                 :: "r"(smem_addr), "l"(gsrc));
}
__device__ __forceinline__ void cp_commit() {
    asm volatile("cp.async.commit_group;\n" ::: "memory");
}
template <int N>
__device__ __forceinline__ void cp_wait() {
    asm volatile("cp.async.wait_group %0;\n" :: "n"(N) : "memory");
}

// ---------------------------------------------------------------------------
__global__ void reset_state_kernel() {
    if (threadIdx.x < 16) g_grp[threadIdx.x] = 0u;
    if (threadIdx.x == 16) g_root[0] = 0u;
    if (threadIdx.x == 17) g_root[1] = 0u;
    if (threadIdx.x == 18) g_sense[0] = 0u;
    if (threadIdx.x == 19) g_sense[1] = 0u;
    if (threadIdx.x == 20) g_tileA = 0u;
    if (threadIdx.x == 21) g_tileB = (unsigned)TILES_PER_Q;
    if (threadIdx.x < 4 + 22 && threadIdx.x >= 22) g_qdone[threadIdx.x - 22] = 0u;
}

// ---------------------------------------------------------------------------
// Per-M-half tree barrier over 64 CTAs: 8 groups of 8 -> root of 8.
// Counters self-reset; sense parity per step (even #rounds -> invariant).
// ---------------------------------------------------------------------------
__device__ __forceinline__ void half_barrier(int bid, int tid, int t) {
    __syncthreads();
    if (tid == 0) {
        const int half = bid >> 6;
        const unsigned ns = ((unsigned)t & 1u) ^ 1u;
        __threadfence();
        unsigned old;
        asm volatile("atom.acq_rel.gpu.global.add.u32 %0, [%1], %2;"
                     : "=r"(old) : "l"(&g_grp[bid >> 3]), "r"(1u) : "memory");
        if (old == 7u) {
            asm volatile("st.relaxed.gpu.global.u32 [%0], %1;"
                         :: "l"(&g_grp[bid >> 3]), "r"(0u) : "memory");
            unsigned rold;
            asm volatile("atom.acq_rel.gpu.global.add.u32 %0, [%1], %2;"
                         : "=r"(rold) : "l"(&g_root[half]), "r"(1u) : "memory");
            if (rold == 7u) {
                asm volatile("st.relaxed.gpu.global.u32 [%0], %1;"
                             :: "l"(&g_root[half]), "r"(0u) : "memory");
                asm volatile("st.release.gpu.global.u32 [%0], %1;"
                             :: "l"(&g_sense[half]), "r"(ns) : "memory");
            } else {
                unsigned v;
                do {
                    asm volatile("ld.acquire.gpu.global.u32 %0, [%1];"
                                 : "=r"(v) : "l"(&g_sense[half]) : "memory");
                } while (v != ns);
            }
        } else {
            unsigned v;
            do {
                asm volatile("ld.acquire.gpu.global.u32 %0, [%1];"
                             : "=r"(v) : "l"(&g_sense[half]) : "memory");
            } while (v != ns);
        }
    }
    __syncthreads();
}

// ---------------------------------------------------------------------------
// One xh tile: tile = q*512 + b*8 + n -> rows [b*512+q*128, +128), cols n*128.
// ---------------------------------------------------------------------------
__device__ void gemm_tile(uint32_t* gsm, const float* __restrict__ X,
                          const float* __restrict__ W, unsigned tile) {
    const int tid  = threadIdx.x;
    const int lane = tid & 31;
    const int wid  = tid >> 5;
    const int wm   = (wid & 3) * 32;
    const int wn   = (wid >> 2) * 32;
    const int gid  = lane >> 2;
    const int tg   = lane & 3;

    const int q  = (int)(tile >> 9);
    const int j  = (int)(tile & 511);
    const int bm = (j >> 3) * TSEQ + q * 128;
    const int bn = (j & 7) * G_BN;

    auto As = [&](int s) { return gsm + s * G_STAGE_WORDS; };
    auto Bs = [&](int s) { return gsm + s * G_STAGE_WORDS + G_BM * GA_STRIDE; };

    auto issue = [&](int k0, int s) {
        uint32_t abase = (uint32_t)__cvta_generic_to_shared(As(s));
        uint32_t bbase = (uint32_t)__cvta_generic_to_shared(Bs(s));
        #pragma unroll
        for (int i = 0; i < 2; i++) {
            int idx = tid + i * 512;
            int r = idx >> 3;
            int c = (idx & 7) * 4;
            cp16(abase + (r * GA_STRIDE + c) * 4,
                 X + (size_t)(bm + r) * DIM + k0 + c);
        }
        #pragma unroll
        for (int i = 0; i < 2; i++) {
            int idx = tid + i * 512;
            int r = idx >> 5;
            int c = (idx & 31) * 4;
            cp16(bbase + (r * GB_STRIDE + c) * 4,
                 W + (size_t)(k0 + r) * DIM + bn + c);
        }
        cp_commit();
    };

    float acc[2][4][4];
    #pragma unroll
    for (int mt = 0; mt < 2; mt++)
        #pragma unroll
        for (int nt = 0; nt < 4; nt++)
            #pragma unroll
            for (int i = 0; i < 4; i++) acc[mt][nt][i] = 0.0f;

    issue(0, 0);
    issue(G_BK, 1);

    const int NKITER = DIM / G_BK;
    for (int kb = 0; kb < NKITER; kb++) {
        if (kb < NKITER - 1) cp_wait<1>(); else cp_wait<0>();
        __syncthreads();

        const uint32_t* A = As(kb & 1);
        const uint32_t* B = Bs(kb & 1);

        #pragma unroll
        for (int k8 = 0; k8 < G_BK; k8 += 8) {
            uint32_t a[2][4], b[4][2];
            #pragma unroll
            for (int mt = 0; mt < 2; mt++) {
                int r = (wm + mt * 16 + gid) * GA_STRIDE;
                a[mt][0] = A[r + k8 + tg];
                a[mt][1] = A[r + 8 * GA_STRIDE + k8 + tg];
                a[mt][2] = A[r + k8 + tg + 4];
                a[mt][3] = A[r + 8 * GA_STRIDE + k8 + tg + 4];
            }
            #pragma unroll
            for (int nt = 0; nt < 4; nt++) {
                int c = wn + nt * 8 + gid;
                b[nt][0] = B[(k8 + tg) * GB_STRIDE + c];
                b[nt][1] = B[(k8 + tg + 4) * GB_STRIDE + c];
            }
            #pragma unroll
            for (int mt = 0; mt < 2; mt++)
                #pragma unroll
                for (int nt = 0; nt < 4; nt++)
                    mma_tf32(acc[mt][nt], a[mt][0], a[mt][1], a[mt][2], a[mt][3],
                             b[nt][0], b[nt][1]);
        }
        __syncthreads();
        if (kb + 2 < NKITER) issue((kb + 2) * G_BK, kb & 1);
    }

    #pragma unroll
    for (int mt = 0; mt < 2; mt++) {
        #pragma unroll
        for (int nt = 0; nt < 4; nt++) {
            int r = bm + wm + mt * 16 + gid;
            int c = bn + wn + nt * 8 + tg * 2;
            *(float2*)(&g_xh[(size_t)r * DIM + c]) =
                make_float2(acc[mt][nt][0], acc[mt][nt][1]);
            *(float2*)(&g_xh[(size_t)(r + 8) * DIM + c]) =
                make_float2(acc[mt][nt][2], acc[mt][nt][3]);
        }
    }
}

// ---------------------------------------------------------------------------
// Recurrence (R11 interior): CTA bid -> mhalf = bid>>6, bn = (bid&63)*16.
// 16 warps = K-sixteenths (64 cols); 2 chunks of 32x32 via private rings.
// 16-way K-reduction in aliased scratch -> flat epilogue -> per-half barrier.
// ---------------------------------------------------------------------------
__device__ void pers_path(uint32_t* smem, const float* __restrict__ Wr,
                          float* __restrict__ OUT, int bid) {
    uint32_t* Bsm  = smem;
    uint32_t* Abuf = smem + BS_WORDS;
    float*    Scr  = (float*)Abuf;

    const int tid   = threadIdx.x;
    const int lane  = tid & 31;
    const int wid   = tid >> 5;
    const int mhalf = bid >> 6;
    const int bn    = (bid & 63) * NTILE;
    const int rbase = mhalf * 32;
    const int ks    = wid;
    const int kbase = ks * 64;
    const int gid   = lane >> 2;
    const int tg    = lane & 3;

    for (int idx = tid; idx < NTILE * DIM; idx += 512) {
        int n = idx & (NTILE - 1);
        int k = idx >> 4;
        Bsm[n * BS_STRIDE + k] = f2tf32(Wr[(size_t)k * DIM + bn + n]);
    }
    __syncthreads();

    // quarter-0 xh must be complete before t=0
    if (tid == 0) {
        unsigned v;
        do {
            asm volatile("ld.acquire.gpu.global.u32 %0, [%1];"
                         : "=r"(v) : "l"(&g_qdone[0]) : "memory");
        } while (v < TILES_PER_Q);
    }
    __syncthreads();

    const uint32_t* Aw = Abuf + wid * 2 * ABUF_WORDS;
    const uint32_t warp_sb = (uint32_t)__cvta_generic_to_shared(Abuf)
                           + wid * 2 * ABUF_WORDS * 4;

    for (int t = 0; t < TSEQ; t++) {
        if ((t & 127) == 0 && t > 0) {
            if (tid == 0) {
                unsigned v;
                do {
                    asm volatile("ld.acquire.gpu.global.u32 %0, [%1];"
                                 : "=r"(v) : "l"(&g_qdone[t >> 7]) : "memory");
                } while (v < TILES_PER_Q);
            }
            __syncthreads();
        }

        float acc[2][2][2][4];
        #pragma unroll
        for (int ch = 0; ch < 2; ch++)
            #pragma unroll
            for (int mt = 0; mt < 2; mt++)
                #pragma unroll
                for (int nt = 0; nt < 2; nt++)
                    #pragma unroll
                    for (int i = 0; i < 4; i++) acc[ch][mt][nt][i] = 0.0f;

        if (t > 0) {
            const float* Hprev = OUT + (size_t)(t - 1) * DIM;

            auto issue = [&](int c) {
                const int k0 = kbase + c * 32;
                const uint32_t base = warp_sb + (c & 1) * ABUF_WORDS * 4;
                #pragma unroll
                for (int i = 0; i < 8; i++) {
                    int idx = lane + i * 32;
                    int r  = idx >> 3;
                    int c4 = idx & 7;
                    cp16(base + (r * A_STRIDE + c4 * 4) * 4,
                         Hprev + (size_t)(rbase + r) * (TSEQ * DIM) + k0 + c4 * 4);
                }
                cp_commit();
            };

            issue(0);
            issue(1);

            #pragma unroll
            for (int c = 0; c < 2; c++) {
                if (c == 0) cp_wait<1>(); else cp_wait<0>();
                __syncwarp();

                const uint32_t* Ab = Aw + (c & 1) * ABUF_WORDS;
                const int kb = kbase + c * 32;

                #pragma unroll
                for (int k8i = 0; k8i < 4; k8i++) {
                    const int kk = k8i * 8;
                    const int ch = k8i & 1;
                    uint32_t a[2][4];
                    #pragma unroll
                    for (int mt = 0; mt < 2; mt++) {
                        int lr = (mt * 16 + gid) * A_STRIDE;
                        a[mt][0] = Ab[lr + kk + tg];
                        a[mt][1] = Ab[lr + 8 * A_STRIDE + kk + tg];
                        a[mt][2] = Ab[lr + kk + tg + 4];
                        a[mt][3] = Ab[lr + 8 * A_STRIDE + kk + tg + 4];
                    }
                    #pragma unroll
                    for (int nt = 0; nt < 2; nt++) {
                        int n = nt * 8 + gid;
                        uint32_t b0 = Bsm[n * BS_STRIDE + kb + kk + tg];
                        uint32_t b1 = Bsm[n * BS_STRIDE + kb + kk + tg + 4];
                        #pragma unroll
                        for (int mt = 0; mt < 2; mt++)
                            mma_tf32(acc[ch][mt][nt], a[mt][0], a[mt][1],
                                     a[mt][2], a[mt][3], b0, b1);
                    }
                }
            }
        }

        float accf[2][2][4];
        #pragma unroll
        for (int mt = 0; mt < 2; mt++)
            #pragma unroll
            for (int nt = 0; nt < 2; nt++)
                #pragma unroll
                for (int i = 0; i < 4; i++)
                    accf[mt][nt][i] = acc[0][mt][nt][i] + acc[1][mt][nt][i];

        __syncthreads();

        #pragma unroll
        for (int mt = 0; mt < 2; mt++) {
            int rg = mt * 16 + gid;
            #pragma unroll
            for (int nt = 0; nt < 2; nt++) {
                int off = ks * 512 + rg * 16 + nt * 8 + tg * 2;
                *(float2*)&Scr[off]       = make_float2(accf[mt][nt][0], accf[mt][nt][1]);
                *(float2*)&Scr[off + 128] = make_float2(accf[mt][nt][2], accf[mt][nt][3]);
            }
        }
        __syncthreads();

        {
            int o   = tid;
            int row = o >> 4;
            int col = o & 15;
            float s = 0.0f;
            #pragma unroll
            for (int p = 0; p < 16; p++) s += Scr[p * 512 + o];
            size_t go = ((size_t)(rbase + row) * TSEQ + t) * DIM + bn + col;
            OUT[go] = sigmoidf_fast(s + g_xh[go]);
        }

        half_barrier(bid, tid, t);
    }
}

// ---------------------------------------------------------------------------
__global__ __launch_bounds__(512, 1) void fused_rnn(const float* __restrict__ X,
                                                    const float* __restrict__ W,
                                                    const float* __restrict__ Wr,
                                                    float* __restrict__ OUT) {
    extern __shared__ uint32_t smem[];
    const int tid = threadIdx.x;
    const int bid = blockIdx.x;

    // ---- Phase A: all CTAs drain quarter-0 tiles ----
    for (;;) {
        if (tid == 0) smem[G_BCAST] = atomicAdd(&g_tileA, 1u);
        __syncthreads();
        const unsigned tile = smem[G_BCAST];
        if (tile >= (unsigned)TILES_PER_Q) break;
        gemm_tile(smem, X, W, tile);
        __threadfence();
        __syncthreads();   // stores fenced; also guards G_BCAST reuse
        if (tid == 0) {
            asm volatile("red.release.gpu.global.add.u32 [%0], %1;"
                         :: "l"(&g_qdone[0]), "r"(1u) : "memory");
        }
    }
    __syncthreads();

    if (bid < NPERS) {
        // ---- Phase B: recurrence ----
        pers_path(smem, Wr, OUT, bid);
    } else {
        // ---- Phase B: workers drain quarters 1..3 ----
        for (;;) {
            if (tid == 0) smem[G_BCAST] = atomicAdd(&g_tileB, 1u);
            __syncthreads();
            const unsigned tile = smem[G_BCAST];
            if (tile >= (unsigned)NTILES) break;
            gemm_tile(smem, X, W, tile);
            __threadfence();
            __syncthreads();
            if (tid == 0) {
                asm volatile("red.release.gpu.global.add.u32 [%0], %1;"
                             :: "l"(&g_qdone[tile >> 9]), "r"(1u) : "memory");
            }
        }
    }
}

// ---------------------------------------------------------------------------
extern "C" void kernel_launch(void* const* d_in, const int* in_sizes, int n_in,
                              void* d_out, int out_size) {
    const float* x  = (const float*)d_in[0];  // [64, 512, 1024]
    const float* w  = (const float*)d_in[1];  // [1024, 1024]
    const float* wr = (const float*)d_in[2];  // [1024, 1024]
    float* out = (float*)d_out;               // [64, 512, 1024]

    cudaFuncSetAttribute(fused_rnn,
                         cudaFuncAttributeMaxDynamicSharedMemorySize,
                         FUSED_SMEM_BYTES);

    reset_state_kernel<<<1, 32>>>();
    fused_rnn<<<NCTA_TOTAL, 512, FUSED_SMEM_BYTES>>>(x, w, wr, out);
}

// round 13
// speedup vs baseline: 1.0859x; 1.0189x over previous
#include <cuda_runtime.h>
#include <cuda_bf16.h>
#include <cstdint>

// ---------------------------------------------------------------------------
// RNN: out[b,t,:] = sigmoid(x@K + h_{t-1}@Wr),  B=64, T=512, D=H=1024
// ONE fused launch, 152 CTAs x 512 threads, hybrid schedule:
//   Phase A: ALL CTAs drain quarter-0 xh tiles (dynamic queue)
//   Phase B: CTAs 0..127 run the recurrence (2 M-halves x 64 N-tiles,
//            per-half tree barriers); CTAs 128..151 finish xh quarters 1..3.
// R13: recurrence interior stripped — B fragments live in REGISTERS for all
//      512 steps (Wr constant), single 32x64 A buffer (one wait/step),
//      single accumulator chain per (mt,nt).
// ---------------------------------------------------------------------------

#define BATCH 64
#define TSEQ  512
#define DIM   1024

#define NCTA_TOTAL 152
#define NPERS      128
#define NTILES     2048
#define TILES_PER_Q 512

// ---- recurrence geometry ----
#define NTILE  16
#define BS_STRIDE 1028
#define BS_WORDS  (NTILE * BS_STRIDE)          // 16448
#define A_STRIDE  68                           // 64 + 4 pad
#define ABUF_WORDS (32 * A_STRIDE)             // 2176: warp buffer 32x64
#define A_REGION_WORDS (16 * ABUF_WORDS)       // 34816
#define FUSED_SMEM_BYTES ((BS_WORDS + A_REGION_WORDS) * 4)   // 205,056 B

// ---- gemm geometry (512 thr: warp grid 4M x 4N, warp tile 32x32) ----
#define G_BM 128
#define G_BN 128
#define G_BK 32
#define GA_STRIDE 36
#define GB_STRIDE 132
#define G_STAGE_WORDS (G_BM * GA_STRIDE + G_BK * GB_STRIDE)   // 8832
#define G_BCAST (2 * G_STAGE_WORDS)

__device__ float g_xh[(size_t)BATCH * TSEQ * DIM];
__device__ unsigned g_tileA;
__device__ unsigned g_tileB;
__device__ unsigned g_qdone[4];
__device__ unsigned g_grp[16];
__device__ unsigned g_root[2];
__device__ unsigned g_sense[2];

__device__ __forceinline__ uint32_t f2tf32(float x) {
    uint32_t r;
    asm("cvt.rna.tf32.f32 %0, %1;" : "=r"(r) : "f"(x));
    return r;
}

__device__ __forceinline__ void mma_tf32(float* d,
                                         uint32_t a0, uint32_t a1, uint32_t a2, uint32_t a3,
                                         uint32_t b0, uint32_t b1) {
    asm volatile(
        "mma.sync.aligned.m16n8k8.row.col.f32.tf32.tf32.f32 "
        "{%0,%1,%2,%3}, {%4,%5,%6,%7}, {%8,%9}, {%0,%1,%2,%3};\n"
        : "+f"(d[0]), "+f"(d[1]), "+f"(d[2]), "+f"(d[3])
        : "r"(a0), "r"(a1), "r"(a2), "r"(a3), "r"(b0), "r"(b1));
}

__device__ __forceinline__ float sigmoidf_fast(float z) {
    return 1.0f / (1.0f + __expf(-z));
}

__device__ __forceinline__ void cp16(uint32_t smem_addr, const void* gsrc) {
    asm volatile("cp.async.cg.shared.global [%0], [%1], 16;\n"
                 :: "r"(smem_addr), "l"(gsrc));
}
__device__ __forceinline__ void cp_commit() {
    asm volatile("cp.async.commit_group;\n" ::: "memory");
}
template <int N>
__device__ __forceinline__ void cp_wait() {
    asm volatile("cp.async.wait_group %0;\n" :: "n"(N) : "memory");
}

// ---------------------------------------------------------------------------
__global__ void reset_state_kernel() {
    if (threadIdx.x < 16) g_grp[threadIdx.x] = 0u;
    if (threadIdx.x == 16) g_root[0] = 0u;
    if (threadIdx.x == 17) g_root[1] = 0u;
    if (threadIdx.x == 18) g_sense[0] = 0u;
    if (threadIdx.x == 19) g_sense[1] = 0u;
    if (threadIdx.x == 20) g_tileA = 0u;
    if (threadIdx.x == 21) g_tileB = (unsigned)TILES_PER_Q;
    if (threadIdx.x >= 22 && threadIdx.x < 26) g_qdone[threadIdx.x - 22] = 0u;
}

// ---------------------------------------------------------------------------
// Per-M-half tree barrier over 64 CTAs: 8 groups of 8 -> root of 8.
// ---------------------------------------------------------------------------
__device__ __forceinline__ void half_barrier(int bid, int tid, int t) {
    __syncthreads();
    if (tid == 0) {
        const int half = bid >> 6;
        const unsigned ns = ((unsigned)t & 1u) ^ 1u;
        __threadfence();
        unsigned old;
        asm volatile("atom.acq_rel.gpu.global.add.u32 %0, [%1], %2;"
                     : "=r"(old) : "l"(&g_grp[bid >> 3]), "r"(1u) : "memory");
        if (old == 7u) {
            asm volatile("st.relaxed.gpu.global.u32 [%0], %1;"
                         :: "l"(&g_grp[bid >> 3]), "r"(0u) : "memory");
            unsigned rold;
            asm volatile("atom.acq_rel.gpu.global.add.u32 %0, [%1], %2;"
                         : "=r"(rold) : "l"(&g_root[half]), "r"(1u) : "memory");
            if (rold == 7u) {
                asm volatile("st.relaxed.gpu.global.u32 [%0], %1;"
                             :: "l"(&g_root[half]), "r"(0u) : "memory");
                asm volatile("st.release.gpu.global.u32 [%0], %1;"
                             :: "l"(&g_sense[half]), "r"(ns) : "memory");
            } else {
                unsigned v;
                do {
                    asm volatile("ld.acquire.gpu.global.u32 %0, [%1];"
                                 : "=r"(v) : "l"(&g_sense[half]) : "memory");
                } while (v != ns);
            }
        } else {
            unsigned v;
            do {
                asm volatile("ld.acquire.gpu.global.u32 %0, [%1];"
                             : "=r"(v) : "l"(&g_sense[half]) : "memory");
            } while (v != ns);
        }
    }
    __syncthreads();
}

// ---------------------------------------------------------------------------
// One xh tile: tile = q*512 + b*8 + n -> rows [b*512+q*128, +128), cols n*128.
// ---------------------------------------------------------------------------
__device__ void gemm_tile(uint32_t* gsm, const float* __restrict__ X,
                          const float* __restrict__ W, unsigned tile) {
    const int tid  = threadIdx.x;
    const int lane = tid & 31;
    const int wid  = tid >> 5;
    const int wm   = (wid & 3) * 32;
    const int wn   = (wid >> 2) * 32;
    const int gid  = lane >> 2;
    const int tg   = lane & 3;

    const int q  = (int)(tile >> 9);
    const int j  = (int)(tile & 511);
    const int bm = (j >> 3) * TSEQ + q * 128;
    const int bn = (j & 7) * G_BN;

    auto As = [&](int s) { return gsm + s * G_STAGE_WORDS; };
    auto Bs = [&](int s) { return gsm + s * G_STAGE_WORDS + G_BM * GA_STRIDE; };

    auto issue = [&](int k0, int s) {
        uint32_t abase = (uint32_t)__cvta_generic_to_shared(As(s));
        uint32_t bbase = (uint32_t)__cvta_generic_to_shared(Bs(s));
        #pragma unroll
        for (int i = 0; i < 2; i++) {
            int idx = tid + i * 512;
            int r = idx >> 3;
            int c = (idx & 7) * 4;
            cp16(abase + (r * GA_STRIDE + c) * 4,
                 X + (size_t)(bm + r) * DIM + k0 + c);
        }
        #pragma unroll
        for (int i = 0; i < 2; i++) {
            int idx = tid + i * 512;
            int r = idx >> 5;
            int c = (idx & 31) * 4;
            cp16(bbase + (r * GB_STRIDE + c) * 4,
                 W + (size_t)(k0 + r) * DIM + bn + c);
        }
        cp_commit();
    };

    float acc[2][4][4];
    #pragma unroll
    for (int mt = 0; mt < 2; mt++)
        #pragma unroll
        for (int nt = 0; nt < 4; nt++)
            #pragma unroll
            for (int i = 0; i < 4; i++) acc[mt][nt][i] = 0.0f;

    issue(0, 0);
    issue(G_BK, 1);

    const int NKITER = DIM / G_BK;
    for (int kb = 0; kb < NKITER; kb++) {
        if (kb < NKITER - 1) cp_wait<1>(); else cp_wait<0>();
        __syncthreads();

        const uint32_t* A = As(kb & 1);
        const uint32_t* B = Bs(kb & 1);

        #pragma unroll
        for (int k8 = 0; k8 < G_BK; k8 += 8) {
            uint32_t a[2][4], b[4][2];
            #pragma unroll
            for (int mt = 0; mt < 2; mt++) {
                int r = (wm + mt * 16 + gid) * GA_STRIDE;
                a[mt][0] = A[r + k8 + tg];
                a[mt][1] = A[r + 8 * GA_STRIDE + k8 + tg];
                a[mt][2] = A[r + k8 + tg + 4];
                a[mt][3] = A[r + 8 * GA_STRIDE + k8 + tg + 4];
            }
            #pragma unroll
            for (int nt = 0; nt < 4; nt++) {
                int c = wn + nt * 8 + gid;
                b[nt][0] = B[(k8 + tg) * GB_STRIDE + c];
                b[nt][1] = B[(k8 + tg + 4) * GB_STRIDE + c];
            }
            #pragma unroll
            for (int mt = 0; mt < 2; mt++)
                #pragma unroll
                for (int nt = 0; nt < 4; nt++)
                    mma_tf32(acc[mt][nt], a[mt][0], a[mt][1], a[mt][2], a[mt][3],
                             b[nt][0], b[nt][1]);
        }
        __syncthreads();
        if (kb + 2 < NKITER) issue((kb + 2) * G_BK, kb & 1);
    }

    #pragma unroll
    for (int mt = 0; mt < 2; mt++) {
        #pragma unroll
        for (int nt = 0; nt < 4; nt++) {
            int r = bm + wm + mt * 16 + gid;
            int c = bn + wn + nt * 8 + tg * 2;
            *(float2*)(&g_xh[(size_t)r * DIM + c]) =
                make_float2(acc[mt][nt][0], acc[mt][nt][1]);
            *(float2*)(&g_xh[(size_t)(r + 8) * DIM + c]) =
                make_float2(acc[mt][nt][2], acc[mt][nt][3]);
        }
    }
}

// ---------------------------------------------------------------------------
// Recurrence: CTA bid -> mhalf = bid>>6 (rows [mhalf*32,+32)), bn=(bid&63)*16.
// 16 warps = K-sixteenths (64 cols). B fragments in REGISTERS (32/warp,
// loaded once). Single 32x64 A buffer per warp, one cp.async wait per step.
// 16-way K-reduction in aliased scratch -> flat epilogue -> per-half barrier.
// ---------------------------------------------------------------------------
__device__ void pers_path(uint32_t* smem, const float* __restrict__ Wr,
                          float* __restrict__ OUT, int bid) {
    uint32_t* Bsm  = smem;
    uint32_t* Abuf = smem + BS_WORDS;
    float*    Scr  = (float*)Abuf;

    const int tid   = threadIdx.x;
    const int lane  = tid & 31;
    const int wid   = tid >> 5;
    const int mhalf = bid >> 6;
    const int bn    = (bid & 63) * NTILE;
    const int rbase = mhalf * 32;
    const int ks    = wid;
    const int kbase = ks * 64;
    const int gid   = lane >> 2;
    const int tg    = lane & 3;

    // Wr slice -> SMEM transposed [n][k], RNA tf32 (once)
    for (int idx = tid; idx < NTILE * DIM; idx += 512) {
        int n = idx & (NTILE - 1);
        int k = idx >> 4;
        Bsm[n * BS_STRIDE + k] = f2tf32(Wr[(size_t)k * DIM + bn + n]);
    }
    __syncthreads();

    // B fragments -> registers (held for all 512 steps): breg[k8i][nt][2]
    uint32_t breg[8][2][2];
    #pragma unroll
    for (int k8i = 0; k8i < 8; k8i++) {
        #pragma unroll
        for (int nt = 0; nt < 2; nt++) {
            int n = nt * 8 + gid;
            breg[k8i][nt][0] = Bsm[n * BS_STRIDE + kbase + k8i * 8 + tg];
            breg[k8i][nt][1] = Bsm[n * BS_STRIDE + kbase + k8i * 8 + tg + 4];
        }
    }

    // quarter-0 xh must be complete before t=0
    if (tid == 0) {
        unsigned v;
        do {
            asm volatile("ld.acquire.gpu.global.u32 %0, [%1];"
                         : "=r"(v) : "l"(&g_qdone[0]) : "memory");
        } while (v < TILES_PER_Q);
    }
    __syncthreads();

    const uint32_t* Aw = Abuf + wid * ABUF_WORDS;
    const uint32_t warp_sb = (uint32_t)__cvta_generic_to_shared(Abuf)
                           + wid * ABUF_WORDS * 4;

    for (int t = 0; t < TSEQ; t++) {
        if ((t & 127) == 0 && t > 0) {
            if (tid == 0) {
                unsigned v;
                do {
                    asm volatile("ld.acquire.gpu.global.u32 %0, [%1];"
                                 : "=r"(v) : "l"(&g_qdone[t >> 7]) : "memory");
                } while (v < TILES_PER_Q);
            }
            __syncthreads();
        }

        float acc[2][2][4];   // [mt][nt][frag]
        #pragma unroll
        for (int mt = 0; mt < 2; mt++)
            #pragma unroll
            for (int nt = 0; nt < 2; nt++)
                #pragma unroll
                for (int i = 0; i < 4; i++) acc[mt][nt][i] = 0.0f;

        if (t > 0) {
            const float* Hprev = OUT + (size_t)(t - 1) * DIM;

            // single A load: 32 rows x 64 cols = 16 cp16/lane
            #pragma unroll
            for (int i = 0; i < 16; i++) {
                int idx = lane + i * 32;
                int r  = idx >> 4;        // 0..31
                int c4 = idx & 15;        // 0..15 (x4 floats)
                cp16(warp_sb + (r * A_STRIDE + c4 * 4) * 4,
                     Hprev + (size_t)(rbase + r) * (TSEQ * DIM) + kbase + c4 * 4);
            }
            cp_commit();
            cp_wait<0>();
            __syncwarp();

            #pragma unroll
            for (int k8i = 0; k8i < 8; k8i++) {
                const int kk = k8i * 8;
                uint32_t a[2][4];
                #pragma unroll
                for (int mt = 0; mt < 2; mt++) {
                    int lr = (mt * 16 + gid) * A_STRIDE;
                    a[mt][0] = Aw[lr + kk + tg];
                    a[mt][1] = Aw[lr + 8 * A_STRIDE + kk + tg];
                    a[mt][2] = Aw[lr + kk + tg + 4];
                    a[mt][3] = Aw[lr + 8 * A_STRIDE + kk + tg + 4];
                }
                #pragma unroll
                for (int nt = 0; nt < 2; nt++) {
                    #pragma unroll
                    for (int mt = 0; mt < 2; mt++)
                        mma_tf32(acc[mt][nt], a[mt][0], a[mt][1], a[mt][2], a[mt][3],
                                 breg[k8i][nt][0], breg[k8i][nt][1]);
                }
            }
        }

        __syncthreads();   // compute done before scratch aliases A buffers

        // partial store: P[ks][row 0..31][col 0..15]
        #pragma unroll
        for (int mt = 0; mt < 2; mt++) {
            int rg = mt * 16 + gid;
            #pragma unroll
            for (int nt = 0; nt < 2; nt++) {
                int off = ks * 512 + rg * 16 + nt * 8 + tg * 2;
                *(float2*)&Scr[off]       = make_float2(acc[mt][nt][0], acc[mt][nt][1]);
                *(float2*)&Scr[off + 128] = make_float2(acc[mt][nt][2], acc[mt][nt][3]);
            }
        }
        __syncthreads();

        // flat epilogue: 512 threads x 1 output
        {
            int o   = tid;
            int row = o >> 4;
            int col = o & 15;
            float s = 0.0f;
            #pragma unroll
            for (int p = 0; p < 16; p++) s += Scr[p * 512 + o];
            size_t go = ((size_t)(rbase + row) * TSEQ + t) * DIM + bn + col;
            OUT[go] = sigmoidf_fast(s + g_xh[go]);
        }

        half_barrier(bid, tid, t);
    }
}

// ---------------------------------------------------------------------------
__global__ __launch_bounds__(512, 1) void fused_rnn(const float* __restrict__ X,
                                                    const float* __restrict__ W,
                                                    const float* __restrict__ Wr,
                                                    float* __restrict__ OUT) {
    extern __shared__ uint32_t smem[];
    const int tid = threadIdx.x;
    const int bid = blockIdx.x;

    // ---- Phase A: all CTAs drain quarter-0 tiles ----
    for (;;) {
        if (tid == 0) smem[G_BCAST] = atomicAdd(&g_tileA, 1u);
        __syncthreads();
        const unsigned tile = smem[G_BCAST];
        if (tile >= (unsigned)TILES_PER_Q) break;
        gemm_tile(smem, X, W, tile);
        __threadfence();
        __syncthreads();
        if (tid == 0) {
            asm volatile("red.release.gpu.global.add.u32 [%0], %1;"
                         :: "l"(&g_qdone[0]), "r"(1u) : "memory");
        }
    }
    __syncthreads();

    if (bid < NPERS) {
        pers_path(smem, Wr, OUT, bid);
    } else {
        for (;;) {
            if (tid == 0) smem[G_BCAST] = atomicAdd(&g_tileB, 1u);
            __syncthreads();
            const unsigned tile = smem[G_BCAST];
            if (tile >= (unsigned)NTILES) break;
            gemm_tile(smem, X, W, tile);
            __threadfence();
            __syncthreads();
            if (tid == 0) {
                asm volatile("red.release.gpu.global.add.u32 [%0], %1;"
                             :: "l"(&g_qdone[tile >> 9]), "r"(1u) : "memory");
            }
        }
    }
}

// ---------------------------------------------------------------------------
extern "C" void kernel_launch(void* const* d_in, const int* in_sizes, int n_in,
                              void* d_out, int out_size) {
    const float* x  = (const float*)d_in[0];  // [64, 512, 1024]
    const float* w  = (const float*)d_in[1];  // [1024, 1024]
    const float* wr = (const float*)d_in[2];  // [1024, 1024]
    float* out = (float*)d_out;               // [64, 512, 1024]

    cudaFuncSetAttribute(fused_rnn,
                         cudaFuncAttributeMaxDynamicSharedMemorySize,
                         FUSED_SMEM_BYTES);

    reset_state_kernel<<<1, 32>>>();
    fused_rnn<<<NCTA_TOTAL, 512, FUSED_SMEM_BYTES>>>(x, w, wr, out);
}